// round 1
// baseline (speedup 1.0000x reference)
#include <cuda_runtime.h>
#include <cstdint>

#define B_ 4
#define C_ 192
#define S_ 64
#define L_ 512
#define SL_ (S_*L_)      // 32768
#define BN 64            // l-columns per block in vout kernel
#define KC 32            // K chunk
#define WST 194          // w_s row stride (8B-aligned rows, 2-way scatter conflicts only)

// ctx scratch: layout [b][s][c]
__device__ float g_ctx[B_*S_*C_];

// ---------- packed fp32x2 helpers (Blackwell f32x2 pipe, PTX-only) ----------
static __device__ __forceinline__ unsigned long long pk2(float x, float y) {
    unsigned long long r;
    asm("mov.b64 %0, {%1,%2};" : "=l"(r) : "r"(__float_as_uint(x)), "r"(__float_as_uint(y)));
    return r;
}
static __device__ __forceinline__ unsigned long long fma2(unsigned long long a,
                                                          unsigned long long b,
                                                          unsigned long long c) {
    unsigned long long d;
    asm("fma.rn.f32x2 %0, %1, %2, %3;" : "=l"(d) : "l"(a), "l"(b), "l"(c));
    return d;
}
static __device__ __forceinline__ float2 upk2(unsigned long long v) {
    unsigned int a, b;
    asm("mov.b64 {%0,%1}, %2;" : "=r"(a), "=r"(b) : "l"(v));
    return make_float2(__uint_as_float(a), __uint_as_float(b));
}

// ============================================================================
// Kernel 1: per (b,s): q = wq·query + bq ; softmax over L ; kctx = key·scores ;
//           ctx = wk @ kctx + bk  -> g_ctx[b][s][c]
// ============================================================================
__global__ __launch_bounds__(256) void ctx_kernel(
    const float* __restrict__ q_in, const float* __restrict__ k_in,
    const float* __restrict__ w, const float* __restrict__ bias)
{
    const int s = blockIdx.x, b = blockIdx.y;
    const int tid = threadIdx.x, lane = tid & 31, warp = tid >> 5;

    __shared__ float sc[L_];
    __shared__ float wq_s[C_];
    __shared__ float kctx_s[C_];
    __shared__ float red8[8];

    if (tid < C_) wq_s[tid] = w[tid];      // wq = row 0 of in_proj_weight
    __syncthreads();

    // ---- q projection: 2 l-positions per thread, coalesced over l ----
    const float* qb = q_in + (size_t)b*C_*SL_ + (size_t)s*L_;
    float a0 = 0.f, a1 = 0.f;
    #pragma unroll 4
    for (int c = 0; c < C_; c++) {
        const float* p = qb + (size_t)c*SL_;
        a0 = fmaf(wq_s[c], p[tid],        a0);
        a1 = fmaf(wq_s[c], p[tid + 256],  a1);
    }
    const float bq = bias[0];
    a0 += bq; a1 += bq;

    // ---- softmax over 512 (block reduce max, then sum) ----
    float m = fmaxf(a0, a1);
    #pragma unroll
    for (int o = 16; o > 0; o >>= 1) m = fmaxf(m, __shfl_xor_sync(0xffffffffu, m, o));
    if (lane == 0) red8[warp] = m;
    __syncthreads();
    float M = red8[0];
    #pragma unroll
    for (int i = 1; i < 8; i++) M = fmaxf(M, red8[i]);

    const float e0 = __expf(a0 - M), e1 = __expf(a1 - M);
    float sm = e0 + e1;
    #pragma unroll
    for (int o = 16; o > 0; o >>= 1) sm += __shfl_xor_sync(0xffffffffu, sm, o);
    __syncthreads();
    if (lane == 0) red8[warp] = sm;
    __syncthreads();
    float T = 0.f;
    #pragma unroll
    for (int i = 0; i < 8; i++) T += red8[i];
    const float inv = 1.0f / T;
    sc[tid]       = e0 * inv;
    sc[tid + 256] = e1 * inv;
    __syncthreads();

    // ---- kctx[c] = sum_l key[b,c,s,l] * scores[l] ; warp per c-stripe ----
    const float* kb = k_in + (size_t)b*C_*SL_ + (size_t)s*L_;
    for (int c = warp; c < C_; c += 8) {
        const float* p = kb + (size_t)c*SL_;
        float acc = 0.f;
        #pragma unroll 4
        for (int l = lane; l < L_; l += 32) acc = fmaf(p[l], sc[l], acc);
        #pragma unroll
        for (int o = 16; o > 0; o >>= 1) acc += __shfl_xor_sync(0xffffffffu, acc, o);
        if (lane == 0) kctx_s[c] = acc;
    }
    __syncthreads();

    // ---- ctx = wk @ kctx + bk  (wk = rows 1..C of in_proj_weight) ----
    if (tid < C_) {
        const float* wr = w + (size_t)(1 + tid) * C_;
        float acc = bias[1 + tid];
        #pragma unroll 8
        for (int c = 0; c < C_; c++) acc = fmaf(wr[c], kctx_s[c], acc);
        g_ctx[((size_t)b*S_ + s)*C_ + tid] = acc;
    }
}

// ============================================================================
// Kernel 2: per block = 64 l-columns of one (b,s):
//   tmp = relu(wv@value + bv) * ctx ;  out = wo@tmp + bo
// f32x2 register-blocked GEMM: 256 thr, per-thread 6 m-pairs x 4 j.
// ============================================================================
__device__ __forceinline__ void gemm_phase(
    const float* __restrict__ wg,   // global weight, row-major [C_][C_]
    const float* __restrict__ Bsm,  // B operand in smem, [C_][BN]
    float* __restrict__ w_s,        // smem transposed weight chunk [KC][WST]
    int tid, int tx, int ty, int m0,
    unsigned long long (&acc)[6][4])
{
    #pragma unroll
    for (int i = 0; i < 6; i++)
        #pragma unroll
        for (int j = 0; j < 4; j++) acc[i][j] = 0ull;

    // prefetch chunk 0 into registers
    float4 pf[6];
    #pragma unroll
    for (int p = 0; p < 6; p++) {
        int idx = p*256 + tid;          // 0..1535
        int kk4 = (idx & 7) << 2;       // 0,4,...,28
        int mm  = idx >> 3;             // 0..191
        pf[p] = *reinterpret_cast<const float4*>(wg + (size_t)mm*C_ + kk4);
    }

    for (int kc = 0; kc < 6; kc++) {
        __syncthreads();                // previous consumers of w_s done
        #pragma unroll
        for (int p = 0; p < 6; p++) {
            int idx = p*256 + tid;
            int kk4 = (idx & 7) << 2;
            int mm  = idx >> 3;
            w_s[(kk4+0)*WST + mm] = pf[p].x;
            w_s[(kk4+1)*WST + mm] = pf[p].y;
            w_s[(kk4+2)*WST + mm] = pf[p].z;
            w_s[(kk4+3)*WST + mm] = pf[p].w;
        }
        __syncthreads();
        if (kc < 5) {                   // prefetch next chunk (latency hidden by compute)
            #pragma unroll
            for (int p = 0; p < 6; p++) {
                int idx = p*256 + tid;
                int kk4 = (idx & 7) << 2;
                int mm  = idx >> 3;
                pf[p] = *reinterpret_cast<const float4*>(
                    wg + (size_t)mm*C_ + (kc+1)*KC + kk4);
            }
        }
        const int kbase = kc * KC;
        #pragma unroll 8
        for (int kk = 0; kk < KC; kk++) {
            // 6 m-pairs of weights, adjacent-m packed, broadcast over tx lanes
            const unsigned long long* wr =
                reinterpret_cast<const unsigned long long*>(&w_s[kk*WST + m0]);
            unsigned long long wp0 = wr[0], wp1 = wr[1], wp2 = wr[2],
                               wp3 = wr[3], wp4 = wr[4], wp5 = wr[5];
            float4 v4 = *reinterpret_cast<const float4*>(&Bsm[(kbase+kk)*BN + tx*4]);
            unsigned long long vd[4] = { pk2(v4.x, v4.x), pk2(v4.y, v4.y),
                                         pk2(v4.z, v4.z), pk2(v4.w, v4.w) };
            #pragma unroll
            for (int j = 0; j < 4; j++) {
                acc[0][j] = fma2(wp0, vd[j], acc[0][j]);
                acc[1][j] = fma2(wp1, vd[j], acc[1][j]);
                acc[2][j] = fma2(wp2, vd[j], acc[2][j]);
                acc[3][j] = fma2(wp3, vd[j], acc[3][j]);
                acc[4][j] = fma2(wp4, vd[j], acc[4][j]);
                acc[5][j] = fma2(wp5, vd[j], acc[5][j]);
            }
        }
    }
}

#define VOUT_SMEM_FLOATS (2*C_*BN + KC*WST + 3*C_)
#define VOUT_SMEM_BYTES  (VOUT_SMEM_FLOATS * 4)

__global__ __launch_bounds__(256, 1) void vout_kernel(
    const float* __restrict__ v_in,
    const float* __restrict__ w_in, const float* __restrict__ bias_in,
    const float* __restrict__ wo,   const float* __restrict__ bo,
    float* __restrict__ out)
{
    extern __shared__ float smp[];
    float* val_s = smp;                  // [C_][BN]
    float* tmp_s = smp + C_*BN;          // [C_][BN]
    float* w_s   = smp + 2*C_*BN;        // [KC][WST]
    float* ctx_s = w_s + KC*WST;         // [C_]
    float* bv_s  = ctx_s + C_;           // [C_]
    float* bo_s  = bv_s + C_;            // [C_]

    const int tid = threadIdx.x;
    const int l0  = blockIdx.x * BN;
    const int s   = blockIdx.y;
    const int b   = blockIdx.z;
    const int tx  = tid & 15;            // j-group (4 cols)
    const int ty  = tid >> 4;            // m-group (12 rows = 6 pairs)
    const int m0  = ty * 12;

    const float* wv = w_in + (size_t)(1 + C_) * C_;   // rows 193..384

    if (tid < C_) {
        ctx_s[tid] = g_ctx[((size_t)b*S_ + s)*C_ + tid];
        bv_s[tid]  = bias_in[1 + C_ + tid];
        bo_s[tid]  = bo[tid];
    }

    // load value tile [C_][BN] into smem (float4, coalesced)
    const float* vb = v_in + (size_t)b*C_*SL_ + (size_t)s*L_ + l0;
    #pragma unroll
    for (int p = 0; p < 12; p++) {
        int idx = p*256 + tid;           // 0..3071
        int c  = idx >> 4;
        int j4 = (idx & 15) << 2;
        float4 v = *reinterpret_cast<const float4*>(vb + (size_t)c*SL_ + j4);
        *reinterpret_cast<float4*>(&val_s[c*BN + j4]) = v;
    }

    unsigned long long acc[6][4];

    // ---- phase 1: v = wv @ value_tile ----
    gemm_phase(wv, val_s, w_s, tid, tx, ty, m0, acc);

    // epilogue 1: relu(v + bv) * ctx -> tmp_s
    #pragma unroll
    for (int i = 0; i < 6; i++) {
        const int m = m0 + 2*i;
        float2 r0 = upk2(acc[i][0]), r1 = upk2(acc[i][1]),
               r2 = upk2(acc[i][2]), r3 = upk2(acc[i][3]);
        const float bvl = bv_s[m],   cl = ctx_s[m];
        const float bvh = bv_s[m+1], ch = ctx_s[m+1];
        float4 lo = make_float4(fmaxf(r0.x + bvl, 0.f) * cl,
                                fmaxf(r1.x + bvl, 0.f) * cl,
                                fmaxf(r2.x + bvl, 0.f) * cl,
                                fmaxf(r3.x + bvl, 0.f) * cl);
        float4 hi = make_float4(fmaxf(r0.y + bvh, 0.f) * ch,
                                fmaxf(r1.y + bvh, 0.f) * ch,
                                fmaxf(r2.y + bvh, 0.f) * ch,
                                fmaxf(r3.y + bvh, 0.f) * ch);
        *reinterpret_cast<float4*>(&tmp_s[(m  )*BN + tx*4]) = lo;
        *reinterpret_cast<float4*>(&tmp_s[(m+1)*BN + tx*4]) = hi;
    }
    // (visibility of tmp_s is guaranteed by the two __syncthreads at the top
    //  of phase 2's first chunk, before any thread reads tmp_s)

    // ---- phase 2: out = wo @ tmp ----
    gemm_phase(wo, tmp_s, w_s, tid, tx, ty, m0, acc);

    // epilogue 2: + bo -> global
    float* ob = out + (size_t)b*C_*SL_ + (size_t)s*L_ + l0;
    #pragma unroll
    for (int i = 0; i < 6; i++) {
        const int m = m0 + 2*i;
        float2 r0 = upk2(acc[i][0]), r1 = upk2(acc[i][1]),
               r2 = upk2(acc[i][2]), r3 = upk2(acc[i][3]);
        const float bl = bo_s[m], bh = bo_s[m+1];
        float4 lo = make_float4(r0.x + bl, r1.x + bl, r2.x + bl, r3.x + bl);
        float4 hi = make_float4(r0.y + bh, r1.y + bh, r2.y + bh, r3.y + bh);
        *reinterpret_cast<float4*>(ob + (size_t)(m  )*SL_ + tx*4) = lo;
        *reinterpret_cast<float4*>(ob + (size_t)(m+1)*SL_ + tx*4) = hi;
    }
}

// ============================================================================
extern "C" void kernel_launch(void* const* d_in, const int* in_sizes, int n_in,
                              void* d_out, int out_size) {
    const float* query = (const float*)d_in[0];
    const float* key   = (const float*)d_in[1];
    const float* value = (const float*)d_in[2];
    const float* w     = (const float*)d_in[3];   // (385,192,1,1)
    const float* bias  = (const float*)d_in[4];   // (385,)
    const float* wo    = (const float*)d_in[5];   // (192,192,1,1)
    const float* bo    = (const float*)d_in[6];   // (192,)
    float* out = (float*)d_out;

    cudaFuncSetAttribute(vout_kernel,
                         cudaFuncAttributeMaxDynamicSharedMemorySize,
                         VOUT_SMEM_BYTES);

    ctx_kernel<<<dim3(S_, B_), 256>>>(query, key, w, bias);
    vout_kernel<<<dim3(L_/BN, S_, B_), 256, VOUT_SMEM_BYTES>>>(
        value, w, bias, wo, bo, out);
}